// round 16
// baseline (speedup 1.0000x reference)
#include <cuda_runtime.h>
#include <cuda_fp16.h>
#include <cstdint>

// ---------------------------------------------------------------------------
// LSTM layer via fp16 mma.sync GEMM (fp32 accum) + fused gate epilogue.
//   gates = concat(a, x) @ [Wf;Wi;Wc;Wo]^T + b     (M=16384, N=4096, K=2048)
//   f,i,o = sigmoid; g = tanh; c' = f*c + i*g; a' = o*tanh(c')
// Output: [o | a' | c'] fp32 (each 16384x1024).
//
// R15: cross-chunk fragment pipelining. The per-chunk __syncthreads phase-
// locks all warps into [LDSM burst | MMA burst] (crossbar and tensor pipe
// alternate idle -> tensor 54%). Fix: prefetch chunk ch+1's kk0 fragments
// during ch's final MMA burst (stage already resident with 3-stage ring and
// CP_WAIT(0) at chunk top), so the tensor pipe restarts immediately after
// each barrier and LDSM spreads across the whole chunk.
// ---------------------------------------------------------------------------

#define M_TILE   128
#define K_TILE   64            // fp16 elements per chunk (128B rows)
#define STAGES   3
#define CHUNKS   32            // K=2048 / 64
#define HD       1024
#define M_TOTAL  16384

#define A_STAGE_BYTES  (128 * 144)
#define B_STAGE_BYTES  (128 * 144)
#define STAGE_BYTES    (A_STAGE_BYTES + B_STAGE_BYTES)   // 36864
#define SMEM_TOTAL     (STAGES * STAGE_BYTES)            // 110592
#define ES             132      // epilogue smem row stride (floats)

#define A_SCALE 0.0625f
#define W_SCALE 16.0f

// fp16 scratch (module-static device memory; allocation-free at launch time)
__device__ __align__(256) __half A16g[(size_t)M_TOTAL * 2048];  // 64 MiB
__device__ __align__(256) __half B16g[(size_t)4096 * 2048];     // 16 MiB

// ---- PTX helpers -----------------------------------------------------------
__device__ __forceinline__ uint32_t smem_u32(const void* p) {
    uint32_t a;
    asm("{ .reg .u64 t; cvta.to.shared.u64 t, %1; cvt.u32.u64 %0, t; }" : "=r"(a) : "l"(p));
    return a;
}

#define CP_ASYNC16(dst_smem, src_gmem) \
    asm volatile("cp.async.cg.shared.global [%0], [%1], 16;" \
        :: "r"((uint32_t)(dst_smem)), "l"(src_gmem) : "memory")
#define CP_COMMIT()  asm volatile("cp.async.commit_group;" ::: "memory")
#define CP_WAIT(n)   asm volatile("cp.async.wait_group %0;" :: "n"(n) : "memory")

#define LDMATRIX_X4(r0, r1, r2, r3, addr) \
    asm volatile("ldmatrix.sync.aligned.m8n8.x4.shared.b16 {%0,%1,%2,%3}, [%4];" \
        : "=r"(r0), "=r"(r1), "=r"(r2), "=r"(r3) : "r"(addr))

__device__ __forceinline__ void mma_fp16(float d[4], const uint32_t a[4],
                                         uint32_t b0, uint32_t b1) {
    asm volatile(
        "mma.sync.aligned.m16n8k16.row.col.f32.f16.f16.f32 "
        "{%0,%1,%2,%3}, {%4,%5,%6,%7}, {%8,%9}, {%0,%1,%2,%3};"
        : "+f"(d[0]), "+f"(d[1]), "+f"(d[2]), "+f"(d[3])
        : "r"(a[0]), "r"(a[1]), "r"(a[2]), "r"(a[3]), "r"(b0), "r"(b1));
}

__device__ __forceinline__ float tanh_fast(float x) {
    float y; asm("tanh.approx.f32 %0, %1;" : "=f"(y) : "f"(x)); return y;
}
__device__ __forceinline__ float sig_fast(float x) {
    return fmaf(tanh_fast(0.5f * x), 0.5f, 0.5f);
}

// ---------------------------------------------------------------------------
// merged prep:
//   blocks [0, 32768):  A16[m][k] = concat(a,x)[m][k] * (1/16)
//   blocks [32768, ..): B16[row][k] = W * 16, row = hblk*128 + gate*32 + hl
__global__ __launch_bounds__(256) void prep_kernel(
    const float* __restrict__ ga, const float* __restrict__ gx,
    const float* __restrict__ Wf, const float* __restrict__ Wi,
    const float* __restrict__ Wc, const float* __restrict__ Wo)
{
    if (blockIdx.x < 32768) {
        const int idx = blockIdx.x * 256 + threadIdx.x;   // 16384 x 512 f4
        const int m = idx >> 9, pos = idx & 511;
        const int k = pos << 2;
        const float* src = (k < 1024) ? (ga + (size_t)m * 1024 + k)
                                      : (gx + (size_t)m * 1024 + (k - 1024));
        const float4 v = *reinterpret_cast<const float4*>(src);
        __half2 h0 = __floats2half2_rn(v.x * A_SCALE, v.y * A_SCALE);
        __half2 h1 = __floats2half2_rn(v.z * A_SCALE, v.w * A_SCALE);
        uint2 u = make_uint2(*reinterpret_cast<uint32_t*>(&h0),
                             *reinterpret_cast<uint32_t*>(&h1));
        *reinterpret_cast<uint2*>(A16g + (size_t)m * 2048 + k) = u;
    } else {
        const int idx = (blockIdx.x - 32768) * 256 + threadIdx.x;  // 4096 x 512
        const int n2 = idx >> 9, pos = idx & 511;
        const int k = pos << 2;
        const int b = n2 >> 7, g = (n2 >> 5) & 3, hl = n2 & 31;
        const float* Wp = (g == 0) ? Wf : (g == 1) ? Wi : (g == 2) ? Wc : Wo;
        const float4 v = *reinterpret_cast<const float4*>(
            Wp + (size_t)(b * 32 + hl) * 2048 + k);
        __half2 h0 = __floats2half2_rn(v.x * W_SCALE, v.y * W_SCALE);
        __half2 h1 = __floats2half2_rn(v.z * W_SCALE, v.w * W_SCALE);
        uint2 u = make_uint2(*reinterpret_cast<uint32_t*>(&h0),
                             *reinterpret_cast<uint32_t*>(&h1));
        *reinterpret_cast<uint2*>(B16g + (size_t)n2 * 2048 + k) = u;
    }
}

// ---------------------------------------------------------------------------
__global__ __launch_bounds__(256, 2) void lstm_fp16_kernel(
    const float* __restrict__ gc,
    const float* __restrict__ bfp, const float* __restrict__ bip,
    const float* __restrict__ bcp, const float* __restrict__ bop,
    float* __restrict__ out)
{
    extern __shared__ char smem[];
    const uint32_t sb = smem_u32(smem);
    const int tid  = threadIdx.x;
    const int lane = tid & 31;
    const int wid  = tid >> 5;
    const int m0 = blockIdx.y * M_TILE;
    const int h0 = blockIdx.x * 32;            // 32 h-cols per CTA

    // 2 (M) x 4 (N) warps of 64x32
    const int wm = (wid >> 2) * 64;
    const int wn = (wid & 3) * 32;

    const int seg = tid & 7;            // 16B segment within 128B k-row
    const int rb  = tid >> 3;           // base row (0..31)

    float acc[4][4][4];
    #pragma unroll
    for (int mt = 0; mt < 4; mt++)
        #pragma unroll
        for (int nt = 0; nt < 4; nt++)
            #pragma unroll
            for (int q = 0; q < 4; q++) acc[mt][nt][q] = 0.0f;

    const __half* Abase = A16g + (size_t)m0 * 2048;
    const __half* Bbase = B16g + (size_t)(blockIdx.x * 128) * 2048;

    auto load_stage = [&](int s, int ch) {
        const uint32_t sAs = sb + s * STAGE_BYTES;
        const uint32_t sBs = sAs + A_STAGE_BYTES;
        const int kh = ch * K_TILE + seg * 8;            // half index in row
        #pragma unroll
        for (int j = 0; j < 4; j++) {                    // A: 128 rows
            const int row = rb + 32 * j;
            CP_ASYNC16(sAs + row * 144 + seg * 16, Abase + (size_t)row * 2048 + kh);
        }
        #pragma unroll
        for (int j = 0; j < 4; j++) {                    // B: 128 rows
            const int n = rb + 32 * j;
            CP_ASYNC16(sBs + n * 144 + seg * 16, Bbase + (size_t)n * 2048 + kh);
        }
        CP_COMMIT();
    };

    // per-warp ldmatrix base addresses (stage-relative offsets)
    const int lrow = lane & 15;
    const int lkb  = (lane >> 4) * 16;
    const uint32_t aoffA = (wm + lrow) * 144 + lkb;      // + 2304*mt + 32*kk
    const uint32_t aoffB = A_STAGE_BYTES + (wn + lrow) * 144 + lkb;

    uint32_t ra[2][4][4], rbf[2][2][4];

    auto frag_load = [&](int buf, uint32_t stage_base, int kk) {
        const uint32_t kb = (uint32_t)kk * 32;
        #pragma unroll
        for (int mt = 0; mt < 4; mt++)
            LDMATRIX_X4(ra[buf][mt][0], ra[buf][mt][1],
                        ra[buf][mt][2], ra[buf][mt][3],
                        stage_base + aoffA + mt * 2304 + kb);
        #pragma unroll
        for (int p = 0; p < 2; p++)
            LDMATRIX_X4(rbf[buf][p][0], rbf[buf][p][1],
                        rbf[buf][p][2], rbf[buf][p][3],
                        stage_base + aoffB + p * 2304 + kb);
    };

    // ---- prologue: stages 0,1 in flight; preload (ch0, kk0) fragments ----
    load_stage(0, 0);
    load_stage(1, 1);
    CP_WAIT(0);
    __syncthreads();
    frag_load(0, sb, 0);

    int s_load = 2, s_comp = 0, cur = 0;
    #pragma unroll 1
    for (int ch = 0; ch < CHUNKS; ch++) {
        if (ch) {
            CP_WAIT(0);          // loads through ch+1 complete
            __syncthreads();     // visibility + oldest stage freed
        }
        const uint32_t sAs = sb + s_comp * STAGE_BYTES;
        const int s_next = (s_comp + 1 == STAGES) ? 0 : s_comp + 1;
        const uint32_t sAn = sb + s_next * STAGE_BYTES;
        s_comp = s_next;

        if (ch + 2 < CHUNKS) {   // refill freed stage
            load_stage(s_load, ch + 2);
            if (++s_load == STAGES) s_load = 0;
        }

        #pragma unroll
        for (int kk = 0; kk < 4; kk++) {                 // 4 x k16
            const int nxt = cur ^ 1;
            if (kk < 3)                 frag_load(nxt, sAs, kk + 1);
            else if (ch + 1 < CHUNKS)   frag_load(nxt, sAn, 0);  // next chunk kk0
            #pragma unroll
            for (int mt = 0; mt < 4; mt++)
                #pragma unroll
                for (int nt = 0; nt < 4; nt++)
                    mma_fp16(acc[mt][nt], ra[cur][mt],
                             rbf[cur][nt >> 1][nt & 1],
                             rbf[cur][nt >> 1][(nt & 1) + 2]);
            cur = nxt;
        }
    }

    // ---- epilogue: stage gates through smem, fuse nonlinearity ----
    CP_WAIT(0);
    __syncthreads();
    float* E = reinterpret_cast<float*>(smem);           // [128][ES]

    #pragma unroll
    for (int mt = 0; mt < 4; mt++) {
        const int r0 = wm + 16 * mt + (lane >> 2);
        #pragma unroll
        for (int nt = 0; nt < 4; nt++) {
            const int cc = wn + 8 * nt + 2 * (lane & 3);
            *reinterpret_cast<float2*>(&E[r0 * ES + cc]) =
                make_float2(acc[mt][nt][0], acc[mt][nt][1]);
            *reinterpret_cast<float2*>(&E[(r0 + 8) * ES + cc]) =
                make_float2(acc[mt][nt][2], acc[mt][nt][3]);
        }
    }
    __syncthreads();

    float* o_out = out;
    float* a_out = out + (size_t)M_TOTAL * HD;
    float* c_out = out + 2 * (size_t)M_TOTAL * HD;

    #pragma unroll 1
    for (int it = 0; it < 4; it++) {
        const int task = tid + 256 * it;                 // 128 m x 8 h-quads
        const int m = task >> 3;
        const int h = (task & 7) * 4;
        const float4 fv = *reinterpret_cast<const float4*>(&E[m * ES + h]);
        const float4 iv = *reinterpret_cast<const float4*>(&E[m * ES + 32 + h]);
        const float4 gv = *reinterpret_cast<const float4*>(&E[m * ES + 64 + h]);
        const float4 ov = *reinterpret_cast<const float4*>(&E[m * ES + 96 + h]);

        const int hg = h0 + h;
        const float4 b_f = *reinterpret_cast<const float4*>(bfp + hg);
        const float4 b_i = *reinterpret_cast<const float4*>(bip + hg);
        const float4 b_c = *reinterpret_cast<const float4*>(bcp + hg);
        const float4 b_o = *reinterpret_cast<const float4*>(bop + hg);

        const size_t base = (size_t)(m0 + m) * HD + hg;
        const float4 cv = *reinterpret_cast<const float4*>(gc + base);

        float fg[4] = {fv.x + b_f.x, fv.y + b_f.y, fv.z + b_f.z, fv.w + b_f.w};
        float ig[4] = {iv.x + b_i.x, iv.y + b_i.y, iv.z + b_i.z, iv.w + b_i.w};
        float gg[4] = {gv.x + b_c.x, gv.y + b_c.y, gv.z + b_c.z, gv.w + b_c.w};
        float og[4] = {ov.x + b_o.x, ov.y + b_o.y, ov.z + b_o.z, ov.w + b_o.w};
        float ci[4] = {cv.x, cv.y, cv.z, cv.w};

        float oo[4], ao[4], co[4];
        #pragma unroll
        for (int q = 0; q < 4; q++) {
            const float f = sig_fast(fg[q]);
            const float i = sig_fast(ig[q]);
            const float g = tanh_fast(gg[q]);
            const float o = sig_fast(og[q]);
            const float cn = fmaf(f, ci[q], i * g);
            oo[q] = o; co[q] = cn; ao[q] = o * tanh_fast(cn);
        }
        *reinterpret_cast<float4*>(o_out + base) = make_float4(oo[0], oo[1], oo[2], oo[3]);
        *reinterpret_cast<float4*>(a_out + base) = make_float4(ao[0], ao[1], ao[2], ao[3]);
        *reinterpret_cast<float4*>(c_out + base) = make_float4(co[0], co[1], co[2], co[3]);
    }
}

// ---------------------------------------------------------------------------
extern "C" void kernel_launch(void* const* d_in, const int* in_sizes, int n_in,
                              void* d_out, int out_size) {
    (void)in_sizes; (void)n_in; (void)out_size;
    const float* x  = (const float*)d_in[0];
    const float* a  = (const float*)d_in[1];
    const float* c  = (const float*)d_in[2];
    const float* Wf = (const float*)d_in[3];
    const float* bf = (const float*)d_in[4];
    const float* Wi = (const float*)d_in[5];
    const float* bi = (const float*)d_in[6];
    const float* Wc = (const float*)d_in[7];
    const float* bc = (const float*)d_in[8];
    const float* Wo = (const float*)d_in[9];
    const float* bo = (const float*)d_in[10];

    static int attr_set = 0;
    if (!attr_set) {
        cudaFuncSetAttribute(lstm_fp16_kernel,
                             cudaFuncAttributeMaxDynamicSharedMemorySize, SMEM_TOTAL);
        attr_set = 1;
    }

    prep_kernel<<<32768 + 8192, 256>>>(a, x, Wf, Wi, Wc, Wo);

    dim3 grid(HD / 32, M_TOTAL / M_TILE);      // (32, 128) = 4096 CTAs
    lstm_fp16_kernel<<<grid, 256, SMEM_TOTAL>>>(
        c, bf, bi, bc, bo, (float*)d_out);
}

// round 17
// speedup vs baseline: 1.1263x; 1.1263x over previous
#include <cuda_runtime.h>
#include <cuda_fp16.h>
#include <cstdint>

// ---------------------------------------------------------------------------
// LSTM layer via fp16 mma.sync GEMM (fp32 accum) + fused gate epilogue.
//   gates = concat(a, x) @ [Wf;Wi;Wc;Wo]^T + b     (M=16384, N=4096, K=2048)
//   f,i,o = sigmoid; g = tanh; c' = f*c + i*g; a' = o*tanh(c')
// Output: [o | a' | c'] fp32 (each 16384x1024).
//
// R17: free-running mbarrier pipeline. The per-chunk __syncthreads phase-
// locked all 16 warps/SM into alternating [L1tex burst | MMA burst] phases
// (tensor pegged at ~52% = 2*1024/4100 cyc). Replaced with per-stage
// full/empty mbarriers (cp.async.mbarrier.arrive.noinc for fills; consumers
// arrive empty after their MMAs) so warps drift ~1 chunk and LDSM/MMA phases
// of different warps overlap. Chunk loop unrolled in rounds of 3 so stage
// bases are compile-time constants (kills per-LDSM address ALU).
// ---------------------------------------------------------------------------

#define M_TILE   128
#define K_TILE   64            // fp16 elements per chunk (128B rows)
#define STAGES   3
#define CHUNKS   32            // K=2048 / 64
#define HD       1024
#define M_TOTAL  16384

#define A_STAGE_BYTES  (128 * 144)
#define B_STAGE_BYTES  (128 * 144)
#define STAGE_BYTES    (A_STAGE_BYTES + B_STAGE_BYTES)   // 36864
#define MBAR_OFF       (STAGES * STAGE_BYTES)            // 110592
#define SMEM_TOTAL     (MBAR_OFF + 64)                   // 110656 (occ 2)
#define ES             132      // epilogue smem row stride (floats)

#define A_SCALE 0.0625f
#define W_SCALE 16.0f

// fp16 scratch (module-static device memory; allocation-free at launch time)
__device__ __align__(256) __half A16g[(size_t)M_TOTAL * 2048];  // 64 MiB
__device__ __align__(256) __half B16g[(size_t)4096 * 2048];     // 16 MiB

// ---- PTX helpers -----------------------------------------------------------
__device__ __forceinline__ uint32_t smem_u32(const void* p) {
    uint32_t a;
    asm("{ .reg .u64 t; cvta.to.shared.u64 t, %1; cvt.u32.u64 %0, t; }" : "=r"(a) : "l"(p));
    return a;
}

#define CP_ASYNC16(dst_smem, src_gmem) \
    asm volatile("cp.async.cg.shared.global [%0], [%1], 16;" \
        :: "r"((uint32_t)(dst_smem)), "l"(src_gmem) : "memory")

#define CP_ASYNC_MBAR_ARRIVE(mbar) \
    asm volatile("cp.async.mbarrier.arrive.noinc.shared.b64 [%0];" \
        :: "r"((uint32_t)(mbar)) : "memory")

#define MBARRIER_INIT(mbar, count) \
    asm volatile("mbarrier.init.shared.b64 [%0], %1;" \
        :: "r"((uint32_t)(mbar)), "r"((uint32_t)(count)) : "memory")

#define MBARRIER_ARRIVE(mbar) \
    asm volatile("mbarrier.arrive.shared.b64 _, [%0];" \
        :: "r"((uint32_t)(mbar)) : "memory")

#define MBARRIER_WAIT_PARITY(mbar, parity) do {                                        \
    uint32_t _m = (uint32_t)(mbar); uint32_t _p = (uint32_t)(parity); uint32_t _d;     \
    asm volatile("{\n\t.reg .pred p;\n\t"                                              \
        "mbarrier.try_wait.parity.acquire.cta.shared::cta.b64 p, [%1], %2;\n\t"        \
        "selp.b32 %0, 1, 0, p;\n\t}" : "=r"(_d) : "r"(_m), "r"(_p) : "memory");        \
    if (!_d) {                                                                          \
        asm volatile("{\n\t.reg .pred P1;\n\t"                                          \
            "WL_%=:\n\t"                                                                \
            "mbarrier.try_wait.parity.acquire.cta.shared::cta.b64 P1, [%0], %1, 0x989680;\n\t" \
            "@P1 bra.uni WD_%=;\n\t"                                                    \
            "bra.uni WL_%=;\n\t"                                                        \
            "WD_%=:\n\t}" :: "r"(_m), "r"(_p) : "memory");                              \
    }                                                                                   \
} while (0)

#define MBARRIER_WAIT_PARITY_RELAXED(mbar, parity) do {                                \
    uint32_t _m = (uint32_t)(mbar); uint32_t _p = (uint32_t)(parity); uint32_t _d;     \
    asm volatile("{\n\t.reg .pred p;\n\t"                                              \
        "mbarrier.try_wait.parity.relaxed.cta.shared::cta.b64 p, [%1], %2, 0x989680;\n\t" \
        "selp.b32 %0, 1, 0, p;\n\t}" : "=r"(_d) : "r"(_m), "r"(_p) : "memory");        \
    if (!_d) {                                                                          \
        asm volatile("{\n\t.reg .pred P1;\n\t"                                          \
            "WL_%=:\n\t"                                                                \
            "mbarrier.try_wait.parity.relaxed.cta.shared::cta.b64 P1, [%0], %1, 0x989680;\n\t" \
            "@P1 bra.uni WD_%=;\n\t"                                                    \
            "bra.uni WL_%=;\n\t"                                                        \
            "WD_%=:\n\t}" :: "r"(_m), "r"(_p) : "memory");                              \
    }                                                                                   \
} while (0)

#define LDMATRIX_X4(r0, r1, r2, r3, addr) \
    asm volatile("ldmatrix.sync.aligned.m8n8.x4.shared.b16 {%0,%1,%2,%3}, [%4];" \
        : "=r"(r0), "=r"(r1), "=r"(r2), "=r"(r3) : "r"(addr))

__device__ __forceinline__ void mma_fp16(float d[4], const uint32_t a[4],
                                         uint32_t b0, uint32_t b1) {
    asm volatile(
        "mma.sync.aligned.m16n8k16.row.col.f32.f16.f16.f32 "
        "{%0,%1,%2,%3}, {%4,%5,%6,%7}, {%8,%9}, {%0,%1,%2,%3};"
        : "+f"(d[0]), "+f"(d[1]), "+f"(d[2]), "+f"(d[3])
        : "r"(a[0]), "r"(a[1]), "r"(a[2]), "r"(a[3]), "r"(b0), "r"(b1));
}

__device__ __forceinline__ float tanh_fast(float x) {
    float y; asm("tanh.approx.f32 %0, %1;" : "=f"(y) : "f"(x)); return y;
}
__device__ __forceinline__ float sig_fast(float x) {
    return fmaf(tanh_fast(0.5f * x), 0.5f, 0.5f);
}

// ---------------------------------------------------------------------------
// merged prep:
//   blocks [0, 32768):  A16[m][k] = concat(a,x)[m][k] * (1/16)
//   blocks [32768, ..): B16[row][k] = W * 16, row = hblk*128 + gate*32 + hl
__global__ __launch_bounds__(256) void prep_kernel(
    const float* __restrict__ ga, const float* __restrict__ gx,
    const float* __restrict__ Wf, const float* __restrict__ Wi,
    const float* __restrict__ Wc, const float* __restrict__ Wo)
{
    if (blockIdx.x < 32768) {
        const int idx = blockIdx.x * 256 + threadIdx.x;   // 16384 x 512 f4
        const int m = idx >> 9, pos = idx & 511;
        const int k = pos << 2;
        const float* src = (k < 1024) ? (ga + (size_t)m * 1024 + k)
                                      : (gx + (size_t)m * 1024 + (k - 1024));
        const float4 v = *reinterpret_cast<const float4*>(src);
        __half2 h0 = __floats2half2_rn(v.x * A_SCALE, v.y * A_SCALE);
        __half2 h1 = __floats2half2_rn(v.z * A_SCALE, v.w * A_SCALE);
        uint2 u = make_uint2(*reinterpret_cast<uint32_t*>(&h0),
                             *reinterpret_cast<uint32_t*>(&h1));
        *reinterpret_cast<uint2*>(A16g + (size_t)m * 2048 + k) = u;
    } else {
        const int idx = (blockIdx.x - 32768) * 256 + threadIdx.x;  // 4096 x 512
        const int n2 = idx >> 9, pos = idx & 511;
        const int k = pos << 2;
        const int b = n2 >> 7, g = (n2 >> 5) & 3, hl = n2 & 31;
        const float* Wp = (g == 0) ? Wf : (g == 1) ? Wi : (g == 2) ? Wc : Wo;
        const float4 v = *reinterpret_cast<const float4*>(
            Wp + (size_t)(b * 32 + hl) * 2048 + k);
        __half2 h0 = __floats2half2_rn(v.x * W_SCALE, v.y * W_SCALE);
        __half2 h1 = __floats2half2_rn(v.z * W_SCALE, v.w * W_SCALE);
        uint2 u = make_uint2(*reinterpret_cast<uint32_t*>(&h0),
                             *reinterpret_cast<uint32_t*>(&h1));
        *reinterpret_cast<uint2*>(B16g + (size_t)n2 * 2048 + k) = u;
    }
}

// ---------------------------------------------------------------------------
__global__ __launch_bounds__(256, 2) void lstm_fp16_kernel(
    const float* __restrict__ gc,
    const float* __restrict__ bfp, const float* __restrict__ bip,
    const float* __restrict__ bcp, const float* __restrict__ bop,
    float* __restrict__ out)
{
    extern __shared__ char smem[];
    const uint32_t sb = smem_u32(smem);
    const int tid  = threadIdx.x;
    const int lane = tid & 31;
    const int wid  = tid >> 5;
    const int m0 = blockIdx.y * M_TILE;
    const int h0 = blockIdx.x * 32;            // 32 h-cols per CTA

    const uint32_t mb_full  = sb + MBAR_OFF;        // 3 x 8B
    const uint32_t mb_empty = sb + MBAR_OFF + 24;   // 3 x 8B

    if (tid == 0) {
        #pragma unroll
        for (int s = 0; s < STAGES; s++) {
            MBARRIER_INIT(mb_full  + 8 * s, 256);
            MBARRIER_INIT(mb_empty + 8 * s, 256);
        }
    }
    __syncthreads();

    // 2 (M) x 4 (N) warps of 64x32
    const int wm = (wid >> 2) * 64;
    const int wn = (wid & 3) * 32;

    const int seg = tid & 7;            // 16B segment within 128B k-row
    const int rb  = tid >> 3;           // base row (0..31)

    float acc[4][4][4];
    #pragma unroll
    for (int mt = 0; mt < 4; mt++)
        #pragma unroll
        for (int nt = 0; nt < 4; nt++)
            #pragma unroll
            for (int q = 0; q < 4; q++) acc[mt][nt][q] = 0.0f;

    // global source row pointers (advance by ch*64 halfs = 128B per chunk)
    const __half* pA[4];
    const __half* pB[4];
    {
        const __half* Abase = A16g + (size_t)m0 * 2048 + seg * 8;
        const __half* Bbase = B16g + (size_t)(blockIdx.x * 128) * 2048 + seg * 8;
        #pragma unroll
        for (int j = 0; j < 4; j++) {
            pA[j] = Abase + (size_t)(rb + 32 * j) * 2048;
            pB[j] = Bbase + (size_t)(rb + 32 * j) * 2048;
        }
    }
    const uint32_t dstA = sb + rb * 144 + seg * 16;               // + s*SB + 4608*j
    const uint32_t dstB = dstA + A_STAGE_BYTES;

    // producer: fill stage s (compile-time) with chunk ch
    auto produce = [&](int s, int ch, int waitpar, bool dowait) {
        if (dowait) MBARRIER_WAIT_PARITY_RELAXED(mb_empty + 8 * s, waitpar);
        const int koff = ch * 64;
        #pragma unroll
        for (int j = 0; j < 4; j++)
            CP_ASYNC16(dstA + s * STAGE_BYTES + j * 4608, pA[j] + koff);
        #pragma unroll
        for (int j = 0; j < 4; j++)
            CP_ASYNC16(dstB + s * STAGE_BYTES + j * 4608, pB[j] + koff);
        CP_ASYNC_MBAR_ARRIVE(mb_full + 8 * s);
    };

    // per-warp ldmatrix offsets (stage-relative)
    const int lrow = lane & 15;
    const int lkb  = (lane >> 4) * 16;
    const uint32_t fA = sb + (wm + lrow) * 144 + lkb;             // + s*SB + 2304*mt + 32*kk
    const uint32_t fB = sb + A_STAGE_BYTES + (wn + lrow) * 144 + lkb;

    // consumer: compute chunk resident in stage s (compile-time)
    auto consume = [&](int s, int par) {
        MBARRIER_WAIT_PARITY(mb_full + 8 * s, par);
        #pragma unroll
        for (int kk = 0; kk < 4; kk++) {
            const uint32_t kb = s * STAGE_BYTES + kk * 32;
            uint32_t ra[4][4], rbf[2][4];
            #pragma unroll
            for (int mt = 0; mt < 4; mt++)
                LDMATRIX_X4(ra[mt][0], ra[mt][1], ra[mt][2], ra[mt][3],
                            fA + kb + mt * 2304);
            #pragma unroll
            for (int p = 0; p < 2; p++)
                LDMATRIX_X4(rbf[p][0], rbf[p][1], rbf[p][2], rbf[p][3],
                            fB + kb + p * 2304);
            #pragma unroll
            for (int mt = 0; mt < 4; mt++)
                #pragma unroll
                for (int nt = 0; nt < 4; nt++)
                    mma_fp16(acc[mt][nt], ra[mt],
                             rbf[nt >> 1][nt & 1], rbf[nt >> 1][(nt & 1) + 2]);
        }
        MBARRIER_ARRIVE(mb_empty + 8 * s);   // after MMAs -> smem reads done
    };

    // prologue: fill stages 0,1 with chunks 0,1
    produce(0, 0, 0, false);
    produce(1, 1, 0, false);

    // mainloop: rounds of 3 chunks, stages compile-time
    #pragma unroll 1
    for (int r = 0; r < 10; r++) {
        const int pr = r & 1, pm = (r - 1) & 1;
        produce(2, 3 * r + 2, pm, r > 0);   // fill p=r
        consume(0, pr);                     // chunk 3r   (fill p=r)
        produce(0, 3 * r + 3, pr, true);    // fill p=r+1
        consume(1, pr);                     // chunk 3r+1
        produce(1, 3 * r + 4, pr, true);    // fill p=r+1
        consume(2, pr);                     // chunk 3r+2
    }
    consume(0, 0);                          // chunk 30 (fill p=10, parity 0)
    consume(1, 0);                          // chunk 31 (fill p=10, parity 0)

    // ---- epilogue: stage gates through smem, fuse nonlinearity ----
    __syncthreads();                        // all warps done; cp.asyncs consumed
    float* E = reinterpret_cast<float*>(smem);           // [128][ES]

    #pragma unroll
    for (int mt = 0; mt < 4; mt++) {
        const int r0 = wm + 16 * mt + (lane >> 2);
        #pragma unroll
        for (int nt = 0; nt < 4; nt++) {
            const int cc = wn + 8 * nt + 2 * (lane & 3);
            *reinterpret_cast<float2*>(&E[r0 * ES + cc]) =
                make_float2(acc[mt][nt][0], acc[mt][nt][1]);
            *reinterpret_cast<float2*>(&E[(r0 + 8) * ES + cc]) =
                make_float2(acc[mt][nt][2], acc[mt][nt][3]);
        }
    }
    __syncthreads();

    float* o_out = out;
    float* a_out = out + (size_t)M_TOTAL * HD;
    float* c_out = out + 2 * (size_t)M_TOTAL * HD;

    #pragma unroll 1
    for (int it = 0; it < 4; it++) {
        const int task = tid + 256 * it;                 // 128 m x 8 h-quads
        const int m = task >> 3;
        const int h = (task & 7) * 4;
        const float4 fv = *reinterpret_cast<const float4*>(&E[m * ES + h]);
        const float4 iv = *reinterpret_cast<const float4*>(&E[m * ES + 32 + h]);
        const float4 gv = *reinterpret_cast<const float4*>(&E[m * ES + 64 + h]);
        const float4 ov = *reinterpret_cast<const float4*>(&E[m * ES + 96 + h]);

        const int hg = h0 + h;
        const float4 b_f = *reinterpret_cast<const float4*>(bfp + hg);
        const float4 b_i = *reinterpret_cast<const float4*>(bip + hg);
        const float4 b_c = *reinterpret_cast<const float4*>(bcp + hg);
        const float4 b_o = *reinterpret_cast<const float4*>(bop + hg);

        const size_t base = (size_t)(m0 + m) * HD + hg;
        const float4 cv = *reinterpret_cast<const float4*>(gc + base);

        float fg[4] = {fv.x + b_f.x, fv.y + b_f.y, fv.z + b_f.z, fv.w + b_f.w};
        float ig[4] = {iv.x + b_i.x, iv.y + b_i.y, iv.z + b_i.z, iv.w + b_i.w};
        float gg[4] = {gv.x + b_c.x, gv.y + b_c.y, gv.z + b_c.z, gv.w + b_c.w};
        float og[4] = {ov.x + b_o.x, ov.y + b_o.y, ov.z + b_o.z, ov.w + b_o.w};
        float ci[4] = {cv.x, cv.y, cv.z, cv.w};

        float oo[4], ao[4], co[4];
        #pragma unroll
        for (int q = 0; q < 4; q++) {
            const float f = sig_fast(fg[q]);
            const float i = sig_fast(ig[q]);
            const float g = tanh_fast(gg[q]);
            const float o = sig_fast(og[q]);
            const float cn = fmaf(f, ci[q], i * g);
            oo[q] = o; co[q] = cn; ao[q] = o * tanh_fast(cn);
        }
        *reinterpret_cast<float4*>(o_out + base) = make_float4(oo[0], oo[1], oo[2], oo[3]);
        *reinterpret_cast<float4*>(a_out + base) = make_float4(ao[0], ao[1], ao[2], ao[3]);
        *reinterpret_cast<float4*>(c_out + base) = make_float4(co[0], co[1], co[2], co[3]);
    }
}

// ---------------------------------------------------------------------------
extern "C" void kernel_launch(void* const* d_in, const int* in_sizes, int n_in,
                              void* d_out, int out_size) {
    (void)in_sizes; (void)n_in; (void)out_size;
    const float* x  = (const float*)d_in[0];
    const float* a  = (const float*)d_in[1];
    const float* c  = (const float*)d_in[2];
    const float* Wf = (const float*)d_in[3];
    const float* bf = (const float*)d_in[4];
    const float* Wi = (const float*)d_in[5];
    const float* bi = (const float*)d_in[6];
    const float* Wc = (const float*)d_in[7];
    const float* bc = (const float*)d_in[8];
    const float* Wo = (const float*)d_in[9];
    const float* bo = (const float*)d_in[10];

    static int attr_set = 0;
    if (!attr_set) {
        cudaFuncSetAttribute(lstm_fp16_kernel,
                             cudaFuncAttributeMaxDynamicSharedMemorySize, SMEM_TOTAL);
        attr_set = 1;
    }

    prep_kernel<<<32768 + 8192, 256>>>(a, x, Wf, Wi, Wc, Wo);

    dim3 grid(HD / 32, M_TOTAL / M_TILE);      // (32, 128) = 4096 CTAs
    lstm_fp16_kernel<<<grid, 256, SMEM_TOTAL>>>(
        c, bf, bi, bc, bo, (float*)d_out);
}